// round 4
// baseline (speedup 1.0000x reference)
#include <cuda_runtime.h>
#include <cstdint>

// Painting: sequential alpha-composite of N=128 RGBA layers onto a ones canvas.
// canvas = canvas*(1-a) + a*poly, a = poly[alpha]*0.8, per-pixel recurrence.
//
// R4: cp.async (LDGSTS.cg) pipeline. Register-resident load batching capped
// DRAM at ~78% (32-reg budget). cp.async keeps in-flight data in SMEM:
// depth-4 pipeline of 2-layer stages (8KB each) -> ~168KB in flight per SM,
// far past the latency-BW knee. Block = 256 consecutive pixels; each thread
// owns 1 pixel for compute and one 16B chunk per layer for loading.

#define OPACITY 0.8f
#define HW        262144      // 512*512
#define NLAYERS   128
#define LPS       2           // layers per stage
#define DEPTH     4           // pipeline stages
#define NSTAGES   (NLAYERS / LPS)   // 64
#define STAGE_FLOATS (LPS * 4 * 256)  // 2048 floats = 8KB

__device__ __forceinline__ void cp_async16(uint32_t smem_addr, const void* gptr)
{
    asm volatile("cp.async.cg.shared.global [%0], [%1], 16;\n"
                 :: "r"(smem_addr), "l"(gptr));
}
__device__ __forceinline__ void cp_commit()
{
    asm volatile("cp.async.commit_group;\n" ::: "memory");
}
__device__ __forceinline__ void cp_wait3()
{
    asm volatile("cp.async.wait_group 3;\n" ::: "memory");
}

__global__ __launch_bounds__(256)
void painting_kernel(const float* __restrict__ polys,
                     float* __restrict__ out)
{
    __shared__ float sbuf[DEPTH][STAGE_FLOATS];

    const int t    = threadIdx.x;
    const int base = blockIdx.x * 256;        // first pixel of this block
    const int c    = t >> 6;                  // channel chunk this thread loads
    const int off  = (t & 63) * 4;            // float offset within 1KB chunk

    // gmem source for (layer l): polys[(l*4 + c)*HW + base + off]
    const float* gsrc0 = polys + (size_t)c * HW + base + off;

    // issue one stage (LPS layers x 1 cp.async.16B per thread per layer)
    auto issue_stage = [&](int stage_idx, float* buf) {
        uint32_t sm = (uint32_t)__cvta_generic_to_shared(buf);
#pragma unroll
        for (int u = 0; u < LPS; ++u) {
            int l = stage_idx * LPS + u;
            const float* src = gsrc0 + (size_t)l * (4 * HW);
            cp_async16(sm + (u * 4096 + c * 1024 + off * 4), src);
        }
    };

    // ---- prologue: fill DEPTH stages ----
#pragma unroll
    for (int k = 0; k < DEPTH; ++k) {
        issue_stage(k, sbuf[k]);
        cp_commit();
    }

    float c0 = 1.f, c1 = 1.f, c2 = 1.f, c3 = 1.f;

    for (int s = 0; s < NSTAGES; ++s) {
        cp_wait3();                 // oldest of 4 pending groups complete
        __syncthreads();            // make stage visible to all threads

        const float* buf = sbuf[s & (DEPTH - 1)];
#pragma unroll
        for (int u = 0; u < LPS; ++u) {
            const float* lb = buf + u * 1024;
            float p0 = lb[t];
            float p1 = lb[256 + t];
            float p2 = lb[512 + t];
            float p3 = lb[768 + t];
            float a  = p3 * OPACITY;
            c0 = fmaf(a, p0 - c0, c0);
            c1 = fmaf(a, p1 - c1, c1);
            c2 = fmaf(a, p2 - c2, c2);
            c3 = fmaf(a, p3 - c3, c3);
        }
        __syncthreads();            // everyone done reading before overwrite

        int ns = s + DEPTH;
        if (ns < NSTAGES)
            issue_stage(ns, sbuf[s & (DEPTH - 1)]);
        cp_commit();                // empty group at tail keeps count aligned
    }

    int p = base + t;
    out[p]          = c0;
    out[HW + p]     = c1;
    out[2 * HW + p] = c2;
    out[3 * HW + p] = c3;
}

extern "C" void kernel_launch(void* const* d_in, const int* in_sizes, int n_in,
                              void* d_out, int out_size)
{
    const float* polys = (const float*)d_in[0];
    float* out = (float*)d_out;

    const int blocks = HW / 256;   // 1024
    painting_kernel<<<blocks, 256>>>(polys, out);
}

// round 5
// speedup vs baseline: 1.0640x; 1.0640x over previous
#include <cuda_runtime.h>
#include <cstdint>

// Painting: sequential alpha-composite of N=128 RGBA layers onto a ones canvas.
// canvas = canvas*(1-a) + a*poly, a = poly[alpha]*0.8, per-pixel recurrence.
//
// R5: warp-autonomous cp.async pipeline. R4's block-wide pipeline was gated
// by 2x __syncthreads per stage (x64 stages) and slowest-warp slot reuse.
// Here each warp owns 32 pixels and loads exactly the 4x128B lines per layer
// it consumes: stage sync is cp.async.wait_group + __syncwarp only. 8
// independent warp pipelines per block, depth 4, 2 layers/stage.

#define OPACITY 0.8f
#define HW        262144            // 512*512
#define NLAYERS   128
#define LPS       2                 // layers per stage
#define DEPTH     4                 // pipeline depth (stages in flight)
#define NSTAGES   (NLAYERS / LPS)   // 64
#define WARP_STAGE_FLOATS (LPS * 4 * 32)   // 256 floats = 1KB

__device__ __forceinline__ void cp_async16(uint32_t smem_addr, const void* gptr)
{
    asm volatile("cp.async.cg.shared.global [%0], [%1], 16;\n"
                 :: "r"(smem_addr), "l"(gptr));
}
__device__ __forceinline__ void cp_commit()
{
    asm volatile("cp.async.commit_group;\n" ::: "memory");
}
__device__ __forceinline__ void cp_wait3()
{
    asm volatile("cp.async.wait_group %0;\n" :: "n"(DEPTH - 1) : "memory");
}

__global__ __launch_bounds__(256)
void painting_kernel(const float* __restrict__ polys,
                     float* __restrict__ out)
{
    // [warp][stage][layer-in-stage][channel][32 floats]
    __shared__ float sbuf[8][DEPTH][WARP_STAGE_FLOATS];   // 32 KB

    const int t    = threadIdx.x;
    const int w    = t >> 5;
    const int lane = t & 31;
    const int pix0 = blockIdx.x * 256 + w * 32;   // this warp's 32 pixels

    // loader role: lane l fetches channel (l>>3), 16B chunk (l&7) of the
    // warp's 128B line for that channel.
    const int lc   = lane >> 3;          // channel 0..3
    const int foff = (lane & 7) * 4;     // float offset 0..28 within 32

    const float* gbase = polys + (size_t)lc * HW + pix0 + foff;

    auto issue_stage = [&](int stage_idx, int slot) {
        uint32_t sm = (uint32_t)__cvta_generic_to_shared(&sbuf[w][slot][0])
                      + (uint32_t)(lc * 32 + foff) * 4u;
#pragma unroll
        for (int u = 0; u < LPS; ++u) {
            int l = stage_idx * LPS + u;
            cp_async16(sm + u * (4 * 32 * 4),          // +512B per layer
                       gbase + (size_t)l * (4 * HW));
        }
    };

    // ---- prologue: fill the pipe ----
#pragma unroll
    for (int k = 0; k < DEPTH; ++k) {
        issue_stage(k, k);
        cp_commit();
    }

    float c0 = 1.f, c1 = 1.f, c2 = 1.f, c3 = 1.f;

    for (int s = 0; s < NSTAGES; ++s) {
        cp_wait3();          // oldest pending stage done (per-thread groups)
        __syncwarp();        // publish across the warp's lanes

        const int slot = s & (DEPTH - 1);
        const float* buf = &sbuf[w][slot][0];
#pragma unroll
        for (int u = 0; u < LPS; ++u) {
            const float* lb = buf + u * 128;
            float p0 = lb[lane];
            float p1 = lb[32 + lane];
            float p2 = lb[64 + lane];
            float p3 = lb[96 + lane];
            float a  = p3 * OPACITY;
            c0 = fmaf(a, p0 - c0, c0);
            c1 = fmaf(a, p1 - c1, c1);
            c2 = fmaf(a, p2 - c2, c2);
            c3 = fmaf(a, p3 - c3, c3);
        }
        __syncwarp();        // all lanes done reading slot before refill

        int ns = s + DEPTH;
        if (ns < NSTAGES)
            issue_stage(ns, slot);
        cp_commit();         // (possibly empty) group keeps wait count aligned
    }

    int p = pix0 + lane;
    out[p]          = c0;
    out[HW + p]     = c1;
    out[2 * HW + p] = c2;
    out[3 * HW + p] = c3;
}

extern "C" void kernel_launch(void* const* d_in, const int* in_sizes, int n_in,
                              void* d_out, int out_size)
{
    const float* polys = (const float*)d_in[0];
    float* out = (float*)d_out;

    const int blocks = HW / 256;   // 1024
    painting_kernel<<<blocks, 256>>>(polys, out);
}